// round 14
// baseline (speedup 1.0000x reference)
#include <cuda_runtime.h>
#include <cuda_fp16.h>
#include <cstdint>

#define IN_      512
#define OUT_     512
#define NB_      16
#define M_TOTAL  1024
#define TM       32
#define TN       32
#define NTHREADS 128
#define NWARPS   4
#define NCHUNK   (IN_ / 64)    // 8

#define W_ELEMS  (NB_ * OUT_ * IN_)   // 4,194,304
#define X_ELEMS  (M_TOTAL * IN_)      // 524,288

// smem: 3 buffers x (A plane + B plane), fp16, 32 rows x 128B each
#define PLANE      4096
#define BUF_BYTES  (2 * PLANE)              // 8 KB
#define OFF_ROWS   (3 * BUF_BYTES)          // 24576: int rows_bank[1024]
#define OFF_BIAS   (OFF_ROWS + M_TOTAL * 4) // 28672
#define SMEM_TOTAL (OFF_BIAS + TN * 4)      // 28800

// fp16 copies of x and w (filled by convert kernel each launch)
__device__ __align__(16) __half g_x16[X_ELEMS];
__device__ __align__(16) __half g_w16[W_ELEMS];

// ---------------- PTX helpers ----------------
__device__ __forceinline__ uint32_t smem_u32(const void* p) {
    uint32_t a;
    asm("{ .reg .u64 t; cvta.to.shared.u64 t, %1; cvt.u32.u64 %0, t; }" : "=r"(a) : "l"(p));
    return a;
}
__device__ __forceinline__ void ldsm4(uint32_t* r, uint32_t addr) {
    asm volatile("ldmatrix.sync.aligned.m8n8.x4.shared.b16 {%0,%1,%2,%3}, [%4];"
        : "=r"(r[0]), "=r"(r[1]), "=r"(r[2]), "=r"(r[3]) : "r"(addr));
}
__device__ __forceinline__ void mma_fp16(float* c, const uint32_t* a, uint32_t b0, uint32_t b1) {
    asm volatile("mma.sync.aligned.m16n8k16.row.col.f32.f16.f16.f32 "
        "{%0,%1,%2,%3}, {%4,%5,%6,%7}, {%8,%9}, {%0,%1,%2,%3};"
        : "+f"(c[0]), "+f"(c[1]), "+f"(c[2]), "+f"(c[3])
        : "r"(a[0]), "r"(a[1]), "r"(a[2]), "r"(a[3]), "r"(b0), "r"(b1));
}
__device__ __forceinline__ void cp_async16(uint32_t dst, const void* src, int srcsize) {
    asm volatile("cp.async.cg.shared.global [%0], [%1], 16, %2;"
        :: "r"(dst), "l"(src), "r"(srcsize) : "memory");
}
#define CP_COMMIT() asm volatile("cp.async.commit_group;" ::: "memory")
#define CP_WAIT(n)  asm volatile("cp.async.wait_group %0;" :: "n"(n) : "memory")

__device__ __forceinline__ uint32_t h2bits(__half2 h) {
    return *reinterpret_cast<uint32_t*>(&h);
}

// ---------------- prep: x, w -> fp16 globals ----------------
__global__ __launch_bounds__(256) void convert_xw(
    const float* __restrict__ x, const float* __restrict__ w)
{
    size_t i = ((size_t)blockIdx.x * 256 + threadIdx.x) * 8;
    const float* src;
    __half* dst;
    if (i < W_ELEMS) { src = w + i; dst = g_w16 + i; }
    else             { size_t j = i - W_ELEMS; src = x + j; dst = g_x16 + j; }
    float4 a = *(const float4*)src;
    float4 b = *(const float4*)(src + 4);
    uint4 o;
    o.x = h2bits(__floats2half2_rn(a.x, a.y));
    o.y = h2bits(__floats2half2_rn(a.z, a.w));
    o.z = h2bits(__floats2half2_rn(b.x, b.y));
    o.w = h2bits(__floats2half2_rn(b.z, b.w));
    *(uint4*)dst = o;
}

// ---------------- fused binning + grouped GEMM (fp16 HMMA, cp.async) ---------
__global__ __launch_bounds__(NTHREADS, 6) void gemm_kernel(
    const int*   __restrict__ sel,    // (1024,)
    const float* __restrict__ bias,   // (NB, OUT)
    float* __restrict__ out)          // (1024, OUT)
{
    extern __shared__ __align__(128) uint8_t smem[];
    int*   rows_bank = (int*)(smem + OFF_ROWS);
    float* bias_s    = (float*)(smem + OFF_BIAS);
    __shared__ int warp_base[NWARPS];
    __shared__ int cnt_s;

    const int tid = threadIdx.x;
    const int lid = tid & 31, wid = tid >> 5;
    const int warp_m = wid & 1;        // 2 m-warps x 16 rows
    const int warp_n = wid >> 1;       // 2 n-warps x 16 cols
    const int g  = blockIdx.y;
    const int n0 = blockIdx.x * TN;
    const int mz = blockIdx.z;         // m-slice within bank (4 slices of 32)

    // ---- deterministic binning: stable compaction, 8 sel values per thread ----
    {
        int4 s0 = *(const int4*)&sel[tid * 8];
        int4 s1 = *(const int4*)&sel[tid * 8 + 4];
        int f0 = (s0.x == g), f1 = (s0.y == g), f2 = (s0.z == g), f3 = (s0.w == g);
        int f4 = (s1.x == g), f5 = (s1.y == g), f6 = (s1.z == g), f7 = (s1.w == g);
        int lc = f0 + f1 + f2 + f3 + f4 + f5 + f6 + f7;
        int inc = lc;
        #pragma unroll
        for (int d = 1; d < 32; d <<= 1) {
            int nv = __shfl_up_sync(0xffffffffu, inc, d);
            if (lid >= d) inc += nv;
        }
        if (lid == 31) warp_base[wid] = inc;
        __syncthreads();
        if (tid == 0) {
            int acc = 0;
            #pragma unroll
            for (int i = 0; i < NWARPS; i++) { int v = warp_base[i]; warp_base[i] = acc; acc += v; }
            cnt_s = acc;
        }
        __syncthreads();
        int p = warp_base[wid] + inc - lc;   // exclusive rank
        int b = tid * 8;
        if (f0) rows_bank[p++] = b + 0;
        if (f1) rows_bank[p++] = b + 1;
        if (f2) rows_bank[p++] = b + 2;
        if (f3) rows_bank[p++] = b + 3;
        if (f4) rows_bank[p++] = b + 4;
        if (f5) rows_bank[p++] = b + 5;
        if (f6) rows_bank[p++] = b + 6;
        if (f7) rows_bank[p++] = b + 7;
    }
    if (tid < TN) bias_s[tid] = bias[g * OUT_ + n0 + tid];
    __syncthreads();
    const int cnt = cnt_s;
    if (mz * TM >= cnt) return;

    const uint32_t sm_b = smem_u32(smem);

    // ---- staging geometry: thread -> (row = tid>>2, two 16B units) ----
    const int st_row = tid >> 2;                 // 0..31
    const int u0     = (tid & 3) * 2;            // units 0..7 (16B each)
    const uint32_t st_msk = (uint32_t)(st_row & 7) << 4;
    const uint32_t dst0 = ((uint32_t)(st_row * 128 + u0 * 16))        ^ st_msk;
    const uint32_t dst1 = ((uint32_t)(st_row * 128 + (u0 + 1) * 16))  ^ st_msk;
    // B source (fp16 weights): row n0+st_row of bank g
    const __half* __restrict__ b_src =
        g_w16 + ((size_t)g * OUT_ + n0 + st_row) * IN_ + u0 * 8;

    // ldmatrix constant address parts (R13-verified)
    const uint32_t swx   = (uint32_t)(lid & 7) * 16;
    const uint32_t khalf = (uint32_t)(lid >> 4) * 16;
    const uint32_t a_off = (uint32_t)(warp_m * 16 + (lid & 15)) * 128;
    const uint32_t b_off = (uint32_t)(warp_n * 16 + (lid & 15)) * 128;

    for (int m0 = mz * TM; m0 < cnt; m0 += 4 * TM) {
        // A source row for staging (one row per thread); invalid -> zero-fill
        int mrow = m0 + st_row;
        int valid = (mrow < cnt);
        int r = valid ? rows_bank[mrow] : 0;
        const __half* __restrict__ a_src = g_x16 + (size_t)r * IN_ + u0 * 8;
        const int asz = valid ? 16 : 0;

        // ---- prologue: issue chunks 0 and 1 ----
        #pragma unroll
        for (int c = 0; c < 2; c++) {
            uint32_t bb = sm_b + (uint32_t)c * BUF_BYTES;
            int k0 = c * 64;   // fp16 elements
            cp_async16(bb + dst0,         a_src + k0,     asz);
            cp_async16(bb + dst1,         a_src + k0 + 8, asz);
            cp_async16(bb + PLANE + dst0, b_src + k0,     16);
            cp_async16(bb + PLANE + dst1, b_src + k0 + 8, 16);
            CP_COMMIT();
        }

        float acc[2][4] = {};

        #pragma unroll 1
        for (int t = 0; t < NCHUNK; t++) {
            // chunk t complete (keep 1 newest group pending mid-loop)
            if (t < NCHUNK - 1) CP_WAIT(1); else CP_WAIT(0);
            __syncthreads();   // all threads' chunk-t data visible; all left compute(t-1)

            // issue chunk t+2 into buf[(t+2)%3] (freed: compute(t-1) done)
            if (t + 2 < NCHUNK) {
                uint32_t bb = sm_b + (uint32_t)((t + 2) % 3) * BUF_BYTES;
                int k0 = (t + 2) * 64;
                cp_async16(bb + dst0,         a_src + k0,     asz);
                cp_async16(bb + dst1,         a_src + k0 + 8, asz);
                cp_async16(bb + PLANE + dst0, b_src + k0,     16);
                cp_async16(bb + PLANE + dst1, b_src + k0 + 8, 16);
                CP_COMMIT();
            }

            // ---- compute chunk t from buf[t%3]: 4 k16 steps, 2 MMAs each ----
            const uint32_t bufB = (uint32_t)(t % 3) * BUF_BYTES;
            const uint32_t a_b = sm_b + bufB + a_off;
            const uint32_t b_b = sm_b + bufB + PLANE + b_off;
            #pragma unroll
            for (int s = 0; s < 4; s++) {
                uint32_t koff = ((uint32_t)(khalf + s * 32)) ^ swx;
                uint32_t ah[4], bh[4];
                ldsm4(ah, a_b + koff);
                ldsm4(bh, b_b + koff);
                mma_fp16(acc[0], ah, bh[0], bh[2]);   // cols +0..7
                mma_fp16(acc[1], ah, bh[1], bh[3]);   // cols +8..15
            }
        }

        // ---- epilogue: scatter rows with bias ----
        {
            int gq = lid >> 2, tq = lid & 3;
            int m_lo = m0 + warp_m * 16 + gq;
            int r0 = (m_lo     < cnt) ? rows_bank[m_lo]     : -1;
            int r1 = (m_lo + 8 < cnt) ? rows_bank[m_lo + 8] : -1;
            #pragma unroll
            for (int nf = 0; nf < 2; nf++) {
                int col = warp_n * 16 + nf * 8 + tq * 2;
                float bb0 = bias_s[col], bb1 = bias_s[col + 1];
                if (r0 >= 0) {
                    float2 v = make_float2(acc[nf][0] + bb0, acc[nf][1] + bb1);
                    *(float2*)&out[(size_t)r0 * OUT_ + n0 + col] = v;
                }
                if (r1 >= 0) {
                    float2 v = make_float2(acc[nf][2] + bb0, acc[nf][3] + bb1);
                    *(float2*)&out[(size_t)r1 * OUT_ + n0 + col] = v;
                }
            }
        }
        __syncthreads();   // buffers fully consumed before next m-pass prologue
    }
}

// ---------------------------------------------------------------------------
extern "C" void kernel_launch(void* const* d_in, const int* in_sizes, int n_in,
                              void* d_out, int out_size) {
    const float* tensor = (const float*)d_in[0];   // (B,S,K,IN) fp32
    const int*   sel    = (const int*)  d_in[1];   // (B,S,K) int32
    const float* weight = (const float*)d_in[2];   // (NB,OUT,IN) fp32
    const float* bias   = (const float*)d_in[3];   // (NB,OUT) fp32
    float*       out    = (float*)d_out;           // (B,S,K,OUT) fp32

    cudaFuncSetAttribute(gemm_kernel, cudaFuncAttributeMaxDynamicSharedMemorySize, SMEM_TOTAL);
    convert_xw<<<(W_ELEMS + X_ELEMS) / 8 / 256, 256>>>(tensor, weight);  // 2304 CTAs
    dim3 grid(OUT_ / TN, NB_, 4);   // (16, 16, 4) = 1024 CTAs
    gemm_kernel<<<grid, NTHREADS, SMEM_TOTAL>>>(sel, bias, out);
}

// round 15
// speedup vs baseline: 1.0021x; 1.0021x over previous
#include <cuda_runtime.h>
#include <cuda_fp16.h>
#include <cstdint>

#define IN_      512
#define OUT_     512
#define NB_      16
#define M_TOTAL  1024
#define TM       32
#define TN       32
#define NTHREADS 128
#define NCHUNK   8             // k-chunks of 64 fp16

#define W_ELEMS  (NB_ * OUT_ * IN_)   // 4,194,304
#define X_ELEMS  (M_TOTAL * IN_)      // 524,288

// smem: 8 chunk buffers, each = A plane (4KB) + B plane (4KB)
#define PLANE      4096
#define BUF_BYTES  (2 * PLANE)        // 8 KB
#define SMEM_TOTAL (NCHUNK * BUF_BYTES)  // 65536

// device globals: fp16 operands + global binning plan
__device__ __align__(16) __half g_x16[X_ELEMS];
__device__ __align__(16) __half g_w16[W_ELEMS];
__device__ int g_rows[NB_ * M_TOTAL];
__device__ int g_cnt[NB_];

// ---------------- PTX helpers ----------------
__device__ __forceinline__ uint32_t smem_u32(const void* p) {
    uint32_t a;
    asm("{ .reg .u64 t; cvta.to.shared.u64 t, %1; cvt.u32.u64 %0, t; }" : "=r"(a) : "l"(p));
    return a;
}
__device__ __forceinline__ void ldsm4(uint32_t* r, uint32_t addr) {
    asm volatile("ldmatrix.sync.aligned.m8n8.x4.shared.b16 {%0,%1,%2,%3}, [%4];"
        : "=r"(r[0]), "=r"(r[1]), "=r"(r[2]), "=r"(r[3]) : "r"(addr));
}
__device__ __forceinline__ void mma_fp16(float* c, const uint32_t* a, uint32_t b0, uint32_t b1) {
    asm volatile("mma.sync.aligned.m16n8k16.row.col.f32.f16.f16.f32 "
        "{%0,%1,%2,%3}, {%4,%5,%6,%7}, {%8,%9}, {%0,%1,%2,%3};"
        : "+f"(c[0]), "+f"(c[1]), "+f"(c[2]), "+f"(c[3])
        : "r"(a[0]), "r"(a[1]), "r"(a[2]), "r"(a[3]), "r"(b0), "r"(b1));
}
__device__ __forceinline__ void cp_async16(uint32_t dst, const void* src, int srcsize) {
    asm volatile("cp.async.cg.shared.global [%0], [%1], 16, %2;"
        :: "r"(dst), "l"(src), "r"(srcsize) : "memory");
}
#define CP_COMMIT() asm volatile("cp.async.commit_group;" ::: "memory")

__device__ __forceinline__ uint32_t h2bits(__half2 h) {
    return *reinterpret_cast<uint32_t*>(&h);
}

// ---------------- prep: x, w -> fp16 globals; block 2304 bins rows ----------
__global__ __launch_bounds__(256) void prep_kernel(
    const float* __restrict__ x, const float* __restrict__ w,
    const int* __restrict__ sel)
{
    if (blockIdx.x == (W_ELEMS + X_ELEMS) / 8 / 256) {
        // ---- binning block: one global, order-free plan (outputs are
        // independent of row ordering, so atomics are safe here) ----
        int tid = threadIdx.x;
        if (tid < NB_) g_cnt[tid] = 0;
        __syncthreads();
        #pragma unroll
        for (int i = 0; i < M_TOTAL / 256; i++) {
            int idx = tid + i * 256;
            int g = sel[idx];
            int p = atomicAdd(&g_cnt[g], 1);
            g_rows[g * M_TOTAL + p] = idx;
        }
        return;
    }
    size_t i = ((size_t)blockIdx.x * 256 + threadIdx.x) * 8;
    const float* src;
    __half* dst;
    if (i < W_ELEMS) { src = w + i; dst = g_w16 + i; }
    else             { size_t j = i - W_ELEMS; src = x + j; dst = g_x16 + j; }
    float4 a = *(const float4*)src;
    float4 b = *(const float4*)(src + 4);
    uint4 o;
    o.x = h2bits(__floats2half2_rn(a.x, a.y));
    o.y = h2bits(__floats2half2_rn(a.z, a.w));
    o.z = h2bits(__floats2half2_rn(b.x, b.y));
    o.w = h2bits(__floats2half2_rn(b.z, b.w));
    *(uint4*)dst = o;
}

// compute one 64-k chunk from buffer T (macro so T stays literal)
#define COMPUTE_CHUNK(T) do {                                                  \
    const uint32_t a_b = sm_b + (uint32_t)(T) * BUF_BYTES + a_off;             \
    const uint32_t b_b = sm_b + (uint32_t)(T) * BUF_BYTES + PLANE + b_off;     \
    _Pragma("unroll")                                                          \
    for (int s = 0; s < 4; s++) {                                              \
        uint32_t koff = ((uint32_t)(khalf + s * 32)) ^ swx;                    \
        uint32_t ah[4], bh[4];                                                 \
        ldsm4(ah, a_b + koff);                                                 \
        ldsm4(bh, b_b + koff);                                                 \
        mma_fp16(acc[0], ah, bh[0], bh[2]);                                    \
        mma_fp16(acc[1], ah, bh[1], bh[3]);                                    \
    }                                                                          \
} while (0)

#define PIPE_STEP(TT, WAITN) do {                                              \
    asm volatile("cp.async.wait_group %0;" :: "n"(WAITN) : "memory");          \
    __syncthreads();                                                           \
    COMPUTE_CHUNK(2 * (TT));                                                   \
    COMPUTE_CHUNK(2 * (TT) + 1);                                               \
} while (0)

// ---------------- grouped GEMM (fp16 HMMA, full-K prefetch) ------------------
__global__ __launch_bounds__(NTHREADS, 3) void gemm_kernel(
    const float* __restrict__ bias,   // (NB, OUT)
    float* __restrict__ out)          // (1024, OUT)
{
    extern __shared__ __align__(128) uint8_t smem[];

    const int tid = threadIdx.x;
    const int lid = tid & 31, wid = tid >> 5;
    const int warp_m = wid & 1;        // 2 m-warps x 16 rows
    const int warp_n = wid >> 1;       // 2 n-warps x 16 cols
    const int g  = blockIdx.y;
    const int n0 = blockIdx.x * TN;
    const int mz = blockIdx.z;         // m-slice (4 slices of 32)

    const int cnt = g_cnt[g];
    if (mz * TM >= cnt) return;

    const uint32_t sm_b = smem_u32(smem);

    // staging geometry (R14-verified): row = tid>>2, two 16B units
    const int st_row = tid >> 2;                 // 0..31
    const int u0     = (tid & 3) * 2;            // 16B units 0..7
    const uint32_t st_msk = (uint32_t)(st_row & 7) << 4;
    const uint32_t dst0 = ((uint32_t)(st_row * 128 + u0 * 16))       ^ st_msk;
    const uint32_t dst1 = ((uint32_t)(st_row * 128 + (u0 + 1) * 16)) ^ st_msk;
    const __half* __restrict__ b_src =
        g_w16 + ((size_t)g * OUT_ + n0 + st_row) * IN_ + u0 * 8;

    // ldmatrix constant address parts (R13/R14-verified)
    const uint32_t swx   = (uint32_t)(lid & 7) * 16;
    const uint32_t khalf = (uint32_t)(lid >> 4) * 16;
    const uint32_t a_off = (uint32_t)(warp_m * 16 + (lid & 15)) * 128;
    const uint32_t b_off = (uint32_t)(warp_n * 16 + (lid & 15)) * 128;

    #pragma unroll 1
    for (int m0 = mz * TM; m0 < cnt; m0 += 4 * TM) {
        int mrow = m0 + st_row;
        int valid = (mrow < cnt);
        int r = valid ? g_rows[g * M_TOTAL + mrow] : 0;   // L2-hot LDG
        const __half* __restrict__ a_src = g_x16 + (size_t)r * IN_ + u0 * 8;
        const int asz = valid ? 16 : 0;

        // ---- prologue: issue the ENTIRE K=512 tile (8 groups) ----
        #pragma unroll
        for (int c = 0; c < NCHUNK; c++) {
            uint32_t bb = sm_b + (uint32_t)c * BUF_BYTES;
            int k0 = c * 64;
            cp_async16(bb + dst0,         a_src + k0,     asz);
            cp_async16(bb + dst1,         a_src + k0 + 8, asz);
            cp_async16(bb + PLANE + dst0, b_src + k0,     16);
            cp_async16(bb + PLANE + dst1, b_src + k0 + 8, 16);
            CP_COMMIT();
        }

        float acc[2][4] = {};
        PIPE_STEP(0, 6);
        PIPE_STEP(1, 4);
        PIPE_STEP(2, 2);
        PIPE_STEP(3, 0);

        // ---- epilogue: scatter rows with bias (direct L2 LDGs) ----
        {
            int gq = lid >> 2, tq = lid & 3;
            int m_lo = m0 + warp_m * 16 + gq;
            int r0 = (m_lo     < cnt) ? g_rows[g * M_TOTAL + m_lo]     : -1;
            int r1 = (m_lo + 8 < cnt) ? g_rows[g * M_TOTAL + m_lo + 8] : -1;
            #pragma unroll
            for (int nf = 0; nf < 2; nf++) {
                int col = warp_n * 16 + nf * 8 + tq * 2;
                float2 bb = *(const float2*)&bias[g * OUT_ + n0 + col];
                if (r0 >= 0) {
                    float2 v = make_float2(acc[nf][0] + bb.x, acc[nf][1] + bb.y);
                    *(float2*)&out[(size_t)r0 * OUT_ + n0 + col] = v;
                }
                if (r1 >= 0) {
                    float2 v = make_float2(acc[nf][2] + bb.x, acc[nf][3] + bb.y);
                    *(float2*)&out[(size_t)r1 * OUT_ + n0 + col] = v;
                }
            }
        }
        __syncthreads();   // buffers fully consumed before a (rare) next m-pass
    }
}

// ---------------------------------------------------------------------------
extern "C" void kernel_launch(void* const* d_in, const int* in_sizes, int n_in,
                              void* d_out, int out_size) {
    const float* tensor = (const float*)d_in[0];   // (B,S,K,IN) fp32
    const int*   sel    = (const int*)  d_in[1];   // (B,S,K) int32
    const float* weight = (const float*)d_in[2];   // (NB,OUT,IN) fp32
    const float* bias   = (const float*)d_in[3];   // (NB,OUT) fp32
    float*       out    = (float*)d_out;           // (B,S,K,OUT) fp32

    cudaFuncSetAttribute(gemm_kernel, cudaFuncAttributeMaxDynamicSharedMemorySize, SMEM_TOTAL);
    prep_kernel<<<(W_ELEMS + X_ELEMS) / 8 / 256 + 1, 256>>>(tensor, weight, sel);
    dim3 grid(OUT_ / TN, NB_, 4);   // (16, 16, 4) = 1024 CTAs
    gemm_kernel<<<grid, NTHREADS, SMEM_TOTAL>>>(bias, out);
}